// round 1
// baseline (speedup 1.0000x reference)
#include <cuda_runtime.h>
#include <math.h>

#define N_NODES 100000
#define N_EDGES 1600000
#define NFEAT 128
#define NHID 64
#define NCLASS 40

// ---- scratch (no allocation allowed; __device__ globals) ----
__device__ __align__(16) float g_deg[N_NODES];      // degree, then unused
__device__ __align__(16) float g_dinv[N_NODES];     // deg^{-1/2} incl self-loop
__device__ __align__(16) float g_A[N_NODES * NHID]; // scaled linear output g = dinv * (x@W)
__device__ __align__(16) float g_B[N_NODES * NHID]; // scatter accumulator
__device__ __align__(16) float g_C[N_NODES * NHID]; // post-activation features

// ---------------------------------------------------------------- utilities
__global__ void zero_kernel(float4* p, int n4) {
    int i = blockIdx.x * blockDim.x + threadIdx.x;
    if (i < n4) p[i] = make_float4(0.f, 0.f, 0.f, 0.f);
}

__global__ void count_deg_kernel(const int* __restrict__ dst) {
    int e = blockIdx.x * blockDim.x + threadIdx.x;
    if (e < N_EDGES) atomicAdd(&g_deg[dst[e]], 1.0f);
}

__global__ void dinv_kernel() {
    int i = blockIdx.x * blockDim.x + threadIdx.x;
    if (i < N_NODES) g_dinv[i] = rsqrtf(g_deg[i] + 1.0f); // +1 self-loop
}

// ------------------------------------------------------------------- GEMM
// out[row, :] = dinv[row] * (X[row, :] @ W)  ; W is K x M row-major.
// One thread per row, W cached in shared memory (broadcast reads).
template <int K, int M>
__global__ void __launch_bounds__(128) gemm_scale_kernel(
    const float* __restrict__ X, const float* __restrict__ W,
    float* __restrict__ out)
{
    __shared__ float Ws[K * M];
    for (int i = threadIdx.x; i < K * M; i += 128) Ws[i] = W[i];
    __syncthreads();

    int row = blockIdx.x * 128 + threadIdx.x;
    if (row >= N_NODES) return;

    float acc[M];
#pragma unroll
    for (int m = 0; m < M; m++) acc[m] = 0.f;

    const float4* x4 = reinterpret_cast<const float4*>(X + (size_t)row * K);
#pragma unroll 1
    for (int k4 = 0; k4 < K / 4; k4++) {
        float4 xv = __ldg(&x4[k4]);
        const float* w0 = &Ws[(k4 * 4 + 0) * M];
        const float* w1 = &Ws[(k4 * 4 + 1) * M];
        const float* w2 = &Ws[(k4 * 4 + 2) * M];
        const float* w3 = &Ws[(k4 * 4 + 3) * M];
#pragma unroll
        for (int m = 0; m < M; m++) {
            float a = acc[m];
            a = fmaf(xv.x, w0[m], a);
            a = fmaf(xv.y, w1[m], a);
            a = fmaf(xv.z, w2[m], a);
            a = fmaf(xv.w, w3[m], a);
            acc[m] = a;
        }
    }

    float s = g_dinv[row];
    float4* o4 = reinterpret_cast<float4*>(out + (size_t)row * M);
#pragma unroll
    for (int m4 = 0; m4 < M / 4; m4++)
        o4[m4] = make_float4(acc[4 * m4 + 0] * s, acc[4 * m4 + 1] * s,
                             acc[4 * m4 + 2] * s, acc[4 * m4 + 3] * s);
}

// ----------------------------------------------------------------- scatter
// acc[dst] += g[src]   (vector reductions, 16B granules)
__device__ __forceinline__ void red_add_v4(float* p, float4 v) {
    asm volatile("red.global.add.v4.f32 [%0], {%1, %2, %3, %4};"
                 :: "l"(p), "f"(v.x), "f"(v.y), "f"(v.z), "f"(v.w)
                 : "memory");
}

__global__ void scatter64_kernel(const float4* __restrict__ g, float* acc,
                                 const int* __restrict__ src,
                                 const int* __restrict__ dst)
{
    int tid = blockIdx.x * blockDim.x + threadIdx.x;
    int e = tid >> 4;          // 16 float4 per 64-float row
    int j = tid & 15;
    if (e >= N_EDGES) return;
    int s = __ldg(&src[e]);
    int d = __ldg(&dst[e]);
    float4 v = __ldg(&g[(size_t)s * 16 + j]);
    red_add_v4(acc + (size_t)d * 64 + j * 4, v);
}

__global__ void scatter40_kernel(const float4* __restrict__ g, float* acc,
                                 const int* __restrict__ src,
                                 const int* __restrict__ dst)
{
    int tid = blockIdx.x * blockDim.x + threadIdx.x;
    int e = tid / 10;          // 10 float4 per 40-float row
    int j = tid - e * 10;
    if (e >= N_EDGES) return;
    int s = __ldg(&src[e]);
    int d = __ldg(&dst[e]);
    float4 v = __ldg(&g[(size_t)s * 10 + j]);
    red_add_v4(acc + (size_t)d * 40 + j * 4, v);
}

// ------------------------------------------------------- post-aggregation
// C = relu(dinv * (B + A) + b)   over N_NODES x 64
__global__ void post_relu_kernel(const float4* __restrict__ A,
                                 const float4* __restrict__ B,
                                 const float* __restrict__ bias,
                                 float4* __restrict__ C)
{
    int idx = blockIdx.x * blockDim.x + threadIdx.x; // over N_NODES*16
    if (idx >= N_NODES * 16) return;
    int row = idx >> 4;
    int m4 = idx & 15;
    float s = __ldg(&g_dinv[row]);
    float4 a = A[idx], b = B[idx];
    float4 bb = __ldg(&reinterpret_cast<const float4*>(bias)[m4]);
    float4 r;
    r.x = fmaxf(fmaf(s, a.x + b.x, bb.x), 0.f);
    r.y = fmaxf(fmaf(s, a.y + b.y, bb.y), 0.f);
    r.z = fmaxf(fmaf(s, a.z + b.z, bb.z), 0.f);
    r.w = fmaxf(fmaf(s, a.w + b.w, bb.w), 0.f);
    C[idx] = r;
}

// --------------------------------------------- final: bias + log_softmax
// out[n, :] = log_softmax(dinv[n]*(B[n,:]+A[n,:]) + b3[:40]) ; one warp/node
__global__ void final_lsm_kernel(const float* __restrict__ A,
                                 const float* __restrict__ B,
                                 const float* __restrict__ b3,
                                 float* __restrict__ out)
{
    int warp = (blockIdx.x * blockDim.x + threadIdx.x) >> 5;
    int lane = threadIdx.x & 31;
    if (warp >= N_NODES) return;
    float s = g_dinv[warp];
    size_t base = (size_t)warp * 40;

    float v0 = s * (A[base + lane] + B[base + lane]) + __ldg(&b3[lane]);
    float v1 = -1e30f;
    if (lane < 8)
        v1 = s * (A[base + 32 + lane] + B[base + 32 + lane]) + __ldg(&b3[32 + lane]);

    float m = fmaxf(v0, v1);
#pragma unroll
    for (int off = 16; off > 0; off >>= 1)
        m = fmaxf(m, __shfl_xor_sync(0xFFFFFFFFu, m, off));

    float e = __expf(v0 - m) + ((lane < 8) ? __expf(v1 - m) : 0.f);
#pragma unroll
    for (int off = 16; off > 0; off >>= 1)
        e += __shfl_xor_sync(0xFFFFFFFFu, e, off);

    float ls = __logf(e);
    out[base + lane] = v0 - m - ls;
    if (lane < 8) out[base + 32 + lane] = v1 - m - ls;
}

// ------------------------------------------------------------------ launch
extern "C" void kernel_launch(void* const* d_in, const int* in_sizes, int n_in,
                              void* d_out, int out_size)
{
    const float* x   = (const float*)d_in[0];
    const int* ei    = (const int*)d_in[1];
    const float* W1  = (const float*)d_in[2];
    const float* b1  = (const float*)d_in[3];
    const float* W2  = (const float*)d_in[4];
    const float* b2  = (const float*)d_in[5];
    const float* W3  = (const float*)d_in[6];
    const float* b3  = (const float*)d_in[7];
    float* out       = (float*)d_out;

    const int* src = ei;
    const int* dst = ei + N_EDGES;

    float* A; cudaGetSymbolAddress((void**)&A, g_A);
    float* B; cudaGetSymbolAddress((void**)&B, g_B);
    float* C; cudaGetSymbolAddress((void**)&C, g_C);
    float* D; cudaGetSymbolAddress((void**)&D, g_deg);

    const int TPB = 256;
    // degrees -> dinv
    zero_kernel<<<(N_NODES / 4 + TPB - 1) / TPB, TPB>>>((float4*)D, N_NODES / 4);
    count_deg_kernel<<<(N_EDGES + TPB - 1) / TPB, TPB>>>(dst);
    dinv_kernel<<<(N_NODES + TPB - 1) / TPB, TPB>>>();

    const int n4_64 = N_NODES * NHID / 4;   // 1.6M float4
    const int n4_40 = N_NODES * NCLASS / 4; // 1.0M float4
    const int gemm_blocks = (N_NODES + 127) / 128;
    const int sc64_blocks = (N_EDGES * 16 + TPB - 1) / TPB;
    const int sc40_blocks = (N_EDGES * 10 + TPB - 1) / TPB;
    const int post_blocks = (N_NODES * 16 + TPB - 1) / TPB;

    // ---- layer 1: x @ W1 ----
    gemm_scale_kernel<NFEAT, NHID><<<gemm_blocks, 128>>>(x, W1, A);
    zero_kernel<<<(n4_64 + TPB - 1) / TPB, TPB>>>((float4*)B, n4_64);
    scatter64_kernel<<<sc64_blocks, TPB>>>((const float4*)A, B, src, dst);
    post_relu_kernel<<<post_blocks, TPB>>>((const float4*)A, (const float4*)B, b1, (float4*)C);

    // ---- layer 2: C @ W2 ----
    gemm_scale_kernel<NHID, NHID><<<gemm_blocks, 128>>>(C, W2, A);
    zero_kernel<<<(n4_64 + TPB - 1) / TPB, TPB>>>((float4*)B, n4_64);
    scatter64_kernel<<<sc64_blocks, TPB>>>((const float4*)A, B, src, dst);
    post_relu_kernel<<<post_blocks, TPB>>>((const float4*)A, (const float4*)B, b2, (float4*)C);

    // ---- layer 3: C @ W3, then log_softmax ----
    gemm_scale_kernel<NHID, NCLASS><<<gemm_blocks, 128>>>(C, W3, A);
    zero_kernel<<<(n4_40 + TPB - 1) / TPB, TPB>>>((float4*)B, n4_40);
    scatter40_kernel<<<sc40_blocks, TPB>>>((const float4*)A, B, src, dst);
    final_lsm_kernel<<<(N_NODES * 32 + TPB - 1) / TPB, TPB>>>(A, B, b3, out);
}